// round 7
// baseline (speedup 1.0000x reference)
#include <cuda_runtime.h>

// ---------------- problem constants ----------------
#define BATCH 1024
#define C0_ 512
#define C1_ 1024
#define K0_ 100
#define K1_ 50
#define KP0 128
#define KP1 64
#define MB0 4
#define MB1 8
#define NBLK0 (BATCH/MB0)      // 256
#define NBLK1 (BATCH/MB1)      // 128
#define NBLKS (NBLK0+NBLK1)    // 384
#define CC 64
#define PITCH0 132
#define PITCH1 68
#define CH1 128                // feat1 staging: channels per chunk
#define CH1_FLT (CH1*49)       // 6272
#define CH1_VEC (CH1_FLT/4)    // 1568

// smem layout (bytes):
// head0: sp[4*512]=8192 | swt 64*132*4=33792 | slg 4*132*4=2112   -> 44096
// head1: sp[8*1024]=32768 | buf(25088) UNION swt 64*68*4=17408 | slg 8*68*4=2176 -> 60032
#define SMEM_H0_SWT  8192
#define SMEM_H0_SLG  (8192+33792)
#define SMEM_H1_X    32768
#define SMEM_H1_SLG  (32768+25088)
#define SMEM_TOTAL   60032

__device__ float    g_accum[4] = {0.f, 0.f, 0.f, 0.f};
__device__ unsigned g_done = 0u;

// ---------------- CE: one warp per row, atomic num/den ----------------
template<int K, int PITCH, int AOFF>
__device__ __forceinline__ void ce_rows(float (*slg)[PITCH], int rows, int m0,
    const int* __restrict__ lut, const float* __restrict__ cw,
    const int* __restrict__ target)
{
    const int w = threadIdx.x >> 5, lane = threadIdx.x & 31;
    if (w < rows) {
        float m = -3.4e38f;
        for (int k = lane; k < K; k += 32) m = fmaxf(m, slg[w][k]);
        #pragma unroll
        for (int o = 16; o; o >>= 1) m = fmaxf(m, __shfl_xor_sync(0xffffffffu, m, o));
        float s = 0.f;
        for (int k = lane; k < K; k += 32) s += __expf(slg[w][k] - m);
        #pragma unroll
        for (int o = 16; o; o >>= 1) s += __shfl_xor_sync(0xffffffffu, s, o);
        if (lane == 0) {
            const int t = lut[target[m0 + w]];
            const float nll = m + __logf(s) - slg[w][t];
            const float wt  = cw[t];
            atomicAdd(&g_accum[AOFF],     wt * nll);
            atomicAdd(&g_accum[AOFF + 1], wt);
        }
    }
}

// ---------------- head0 block: pool 4 rows of feat0 + GEMM + CE -----------
__device__ __forceinline__ void head0_block(
    const float* __restrict__ feat0, const float* __restrict__ W,
    const float* __restrict__ bias, const int* __restrict__ lut,
    const float* __restrict__ cw, const int* __restrict__ target,
    int blk, char* sm)
{
    float* sp            = (float*)sm;                       // [MB0*C0_]
    float (*swt)[PITCH0] = (float(*)[PITCH0])(sm + SMEM_H0_SWT);
    float (*slg)[PITCH0] = (float(*)[PITCH0])(sm + SMEM_H0_SLG);

    const int tid = threadIdx.x;
    const int w = tid >> 5, lane = tid & 31;
    const int m0 = blk * MB0;

    // phase A: warp per (b,c) row (49 float4), 2 rows per iteration
    const float4* base = (const float4*)feat0 + (size_t)m0 * (C0_ * 49);
    for (int rr = w * 2; rr < MB0 * C0_; rr += 16) {
        const float4* s0 = base + (size_t)rr * 49;
        float4 a0 = __ldcs(s0 + lane);
        float4 a1 = __ldcs(s0 + 49 + lane);
        float x0 = (a0.x + a0.y) + (a0.z + a0.w);
        float x1 = (a1.x + a1.y) + (a1.z + a1.w);
        if (lane < 17) {
            float4 c0 = __ldcs(s0 + 32 + lane);
            float4 c1 = __ldcs(s0 + 81 + lane);
            x0 += (c0.x + c0.y) + (c0.z + c0.w);
            x1 += (c1.x + c1.y) + (c1.z + c1.w);
        }
        #pragma unroll
        for (int o = 16; o; o >>= 1) {
            x0 += __shfl_xor_sync(0xffffffffu, x0, o);
            x1 += __shfl_xor_sync(0xffffffffu, x1, o);
        }
        if (lane == 0) {
            sp[rr]     = x0 * (1.f / 196.f);
            sp[rr + 1] = x1 * (1.f / 196.f);
        }
    }
    __syncthreads();

    // phase B: GEMM. 4 b-rows x 64 k-groups, TK=2
    const int ktg = tid & 63, bt = tid >> 6;
    float acc0 = 0.f, acc1 = 0.f;
    for (int c0 = 0; c0 < C0_; c0 += CC) {
        #pragma unroll 4
        for (int idx = tid; idx < KP0 * CC; idx += 256) {
            const int c = idx & 63, k = idx >> 6;
            swt[c][k] = (k < K0_) ? W[(size_t)k * C0_ + c0 + c] : 0.f;
        }
        __syncthreads();
        #pragma unroll
        for (int c4 = 0; c4 < CC / 4; c4++) {
            float4 pv = *(const float4*)&sp[bt * C0_ + c0 + c4 * 4];
            float2 w0 = *(const float2*)&swt[c4 * 4 + 0][ktg * 2];
            float2 w1 = *(const float2*)&swt[c4 * 4 + 1][ktg * 2];
            float2 w2 = *(const float2*)&swt[c4 * 4 + 2][ktg * 2];
            float2 w3 = *(const float2*)&swt[c4 * 4 + 3][ktg * 2];
            acc0 = fmaf(pv.x, w0.x, acc0); acc1 = fmaf(pv.x, w0.y, acc1);
            acc0 = fmaf(pv.y, w1.x, acc0); acc1 = fmaf(pv.y, w1.y, acc1);
            acc0 = fmaf(pv.z, w2.x, acc0); acc1 = fmaf(pv.z, w2.y, acc1);
            acc0 = fmaf(pv.w, w3.x, acc0); acc1 = fmaf(pv.w, w3.y, acc1);
        }
        __syncthreads();
    }
    {
        const int k = ktg * 2;
        slg[bt][k]     = acc0 + ((k     < K0_) ? bias[k]     : 0.f);
        slg[bt][k + 1] = acc1 + ((k + 1 < K0_) ? bias[k + 1] : 0.f);
    }
    __syncthreads();
    ce_rows<K0_, PITCH0, 0>(slg, MB0, m0, lut, cw, target);
    __syncthreads();
}

// ---------------- head1 block: pool 8 rows of feat1 + GEMM + CE -----------
__device__ __forceinline__ void head1_block(
    const float* __restrict__ feat1, const float* __restrict__ W,
    const float* __restrict__ bias, const int* __restrict__ lut,
    const float* __restrict__ cw, const int* __restrict__ target,
    int blk, char* sm)
{
    float* sp            = (float*)sm;                       // [MB1*C1_]
    float* buf           = (float*)(sm + SMEM_H1_X);         // CH1_FLT floats
    float (*swt)[PITCH1] = (float(*)[PITCH1])(sm + SMEM_H1_X); // union w/ buf
    float (*slg)[PITCH1] = (float(*)[PITCH1])(sm + SMEM_H1_SLG);

    const int tid = threadIdx.x;
    const int m0 = blk * MB1;

    // phase A: per b, stage 128-channel contiguous chunks, thread-per-row sum
    for (int b = 0; b < MB1; b++) {
        const float4* src = (const float4*)(feat1 + (size_t)(m0 + b) * (C1_ * 49));
        for (int ch = 0; ch < C1_; ch += CH1) {
            const float4* s = src + (ch * 49) / 4;
            float4* d = (float4*)buf;
            #pragma unroll 4
            for (int i = tid; i < CH1_VEC; i += 256) d[i] = __ldcs(s + i);
            __syncthreads();
            if (tid < CH1) {
                const float* r = buf + tid * 49;
                float s0 = 0.f, s1 = 0.f, s2 = 0.f, s3 = 0.f;
                #pragma unroll
                for (int e = 0; e < 48; e += 4) {
                    s0 += r[e]; s1 += r[e + 1]; s2 += r[e + 2]; s3 += r[e + 3];
                }
                sp[b * C1_ + ch + tid] = (s0 + s1 + s2 + s3 + r[48]) * (1.f / 49.f);
            }
            __syncthreads();
        }
    }

    // phase B: GEMM. 4 b-groups x 2 rows x 64 k-groups, TK=1
    const int ktg = tid & 63, bt = tid >> 6;
    float acc0 = 0.f, acc1 = 0.f;
    for (int c0 = 0; c0 < C1_; c0 += CC) {
        #pragma unroll 4
        for (int idx = tid; idx < KP1 * CC; idx += 256) {
            const int c = idx & 63, k = idx >> 6;
            swt[c][k] = (k < K1_) ? W[(size_t)k * C1_ + c0 + c] : 0.f;
        }
        __syncthreads();
        #pragma unroll
        for (int c4 = 0; c4 < CC / 4; c4++) {
            float4 p0 = *(const float4*)&sp[(bt * 2 + 0) * C1_ + c0 + c4 * 4];
            float4 p1 = *(const float4*)&sp[(bt * 2 + 1) * C1_ + c0 + c4 * 4];
            float w0 = swt[c4 * 4 + 0][ktg];
            float w1 = swt[c4 * 4 + 1][ktg];
            float w2 = swt[c4 * 4 + 2][ktg];
            float w3 = swt[c4 * 4 + 3][ktg];
            acc0 = fmaf(p0.x, w0, acc0); acc1 = fmaf(p1.x, w0, acc1);
            acc0 = fmaf(p0.y, w1, acc0); acc1 = fmaf(p1.y, w1, acc1);
            acc0 = fmaf(p0.z, w2, acc0); acc1 = fmaf(p1.z, w2, acc1);
            acc0 = fmaf(p0.w, w3, acc0); acc1 = fmaf(p1.w, w3, acc1);
        }
        __syncthreads();
    }
    {
        const float bv = (ktg < K1_) ? bias[ktg] : 0.f;
        slg[bt * 2 + 0][ktg] = acc0 + bv;
        slg[bt * 2 + 1][ktg] = acc1 + bv;
    }
    __syncthreads();
    ce_rows<K1_, PITCH1, 2>(slg, MB1, m0, lut, cw, target);
    __syncthreads();
}

// ---------------- single fused kernel ----------------
extern "C" __global__ void __launch_bounds__(256)
fused_kernel(const float* __restrict__ feat0, const float* __restrict__ feat1,
             const float* __restrict__ W0, const float* __restrict__ b0,
             const float* __restrict__ W1, const float* __restrict__ b1,
             const int* __restrict__ lut0, const int* __restrict__ lut1,
             const float* __restrict__ cw0, const float* __restrict__ cw1,
             const int* __restrict__ target, float* __restrict__ out)
{
    extern __shared__ char sm[];
    if (blockIdx.x < NBLK0)
        head0_block(feat0, W0, b0, lut0, cw0, target, blockIdx.x, sm);
    else
        head1_block(feat1, W1, b1, lut1, cw1, target, blockIdx.x - NBLK0, sm);

    // last block finalizes and resets state for the next graph replay
    if (threadIdx.x == 0) {
        __threadfence();
        const unsigned arrived = atomicAdd(&g_done, 1u);
        if (arrived == NBLKS - 1u) {
            const float n0 = atomicAdd(&g_accum[0], 0.f);
            const float d0 = atomicAdd(&g_accum[1], 0.f);
            const float n1 = atomicAdd(&g_accum[2], 0.f);
            const float d1 = atomicAdd(&g_accum[3], 0.f);
            out[0] = n0 / d0 + n1 / d1;
            atomicExch(&g_accum[0], 0.f);
            atomicExch(&g_accum[1], 0.f);
            atomicExch(&g_accum[2], 0.f);
            atomicExch(&g_accum[3], 0.f);
            __threadfence();
            atomicExch(&g_done, 0u);
        }
    }
}

// ---------------- launch ----------------
extern "C" void kernel_launch(void* const* d_in, const int* in_sizes, int n_in,
                              void* d_out, int out_size) {
    (void)in_sizes; (void)n_in; (void)out_size;
    const float* feat0  = (const float*)d_in[0];
    const float* feat1  = (const float*)d_in[1];
    const float* W0     = (const float*)d_in[2];
    const float* b0v    = (const float*)d_in[3];
    const float* W1     = (const float*)d_in[4];
    const float* b1v    = (const float*)d_in[5];
    const int*   lut0   = (const int*)d_in[6];
    const int*   lut1   = (const int*)d_in[7];
    const float* cw0    = (const float*)d_in[8];
    const float* cw1    = (const float*)d_in[9];
    const int*   target = (const int*)d_in[10];
    float* out = (float*)d_out;

    cudaFuncSetAttribute(fused_kernel,
                         cudaFuncAttributeMaxDynamicSharedMemorySize, SMEM_TOTAL);
    fused_kernel<<<NBLKS, 256, SMEM_TOTAL>>>(feat0, feat1, W0, b0v, W1, b1v,
                                             lut0, lut1, cw0, cw1, target, out);
}

// round 8
// speedup vs baseline: 1.4465x; 1.4465x over previous
#include <cuda_runtime.h>

// ---------------- problem constants ----------------
#define BATCH 1024
#define C0_ 512
#define C1_ 1024
#define K0_ 100
#define K1_ 50
#define KP0 128
#define KP1 64
#define ROWS0 (BATCH*C0_)   // 524288
#define ROWS1 (BATCH*C1_)   // 1048576

#define MB 16
#define CC 64
#define PITCH0 132
#define PITCH1 68

// ---------------- scratch (no allocation allowed) ----------------
__device__ float g_pooled0[ROWS0];
__device__ float g_pooled1[ROWS1];
__device__ float g_accum[4] = {0.f, 0.f, 0.f, 0.f};
__device__ unsigned g_done = 0u;

// ---------------- fused pooling ----------------
// Blocks [0, NB0): warp per (b,c) row of feat0 (49 float4/row).
// Blocks [NB0, NB0+NB1): 128 feat1 rows staged in 25KB smem (8 blocks/SM ok),
// thread-per-row sum (bank-stride 17: conflict-free).
#define NB0 ((ROWS0*32)/256)    // 65536
#define P1_RPB 128
#define P1_FLT (P1_RPB*49)      // 6272
#define P1_VEC (P1_FLT/4)       // 1568
#define NB1 (ROWS1/P1_RPB)      // 8192

__global__ void __launch_bounds__(256)
pool_kernel(const float* __restrict__ feat0, const float* __restrict__ feat1) {
    __shared__ float sf[P1_FLT];
    if (blockIdx.x == 0 && threadIdx.x < 5) {
        if (threadIdx.x < 4) g_accum[threadIdx.x] = 0.0f;
        else g_done = 0u;
    }
    if (blockIdx.x < NB0) {
        const unsigned wid  = (blockIdx.x * 256u + threadIdx.x) >> 5;
        const unsigned lane = threadIdx.x & 31u;
        const float4* src = reinterpret_cast<const float4*>(feat0) + (size_t)wid * 49;
        float4 a = __ldcs(src + lane);
        float  s = (a.x + a.y) + (a.z + a.w);
        if (lane < 17u) {
            float4 c = __ldcs(src + 32u + lane);
            s += (c.x + c.y) + (c.z + c.w);
        }
        #pragma unroll
        for (int o = 16; o; o >>= 1) s += __shfl_xor_sync(0xffffffffu, s, o);
        if (lane == 0u) g_pooled0[wid] = s * (1.0f / 196.0f);
    } else {
        const unsigned blk = blockIdx.x - NB0;
        const float4* src = reinterpret_cast<const float4*>(feat1) + (size_t)blk * P1_VEC;
        float4* dst = reinterpret_cast<float4*>(sf);
        #pragma unroll 4
        for (int i = threadIdx.x; i < P1_VEC; i += 256)
            dst[i] = __ldcs(src + i);
        __syncthreads();
        const int t = threadIdx.x;
        if (t < P1_RPB) {
            const float* r = sf + t * 49;
            float s0 = 0.f, s1 = 0.f, s2 = 0.f, s3 = 0.f;
            #pragma unroll
            for (int e = 0; e < 48; e += 4) {
                s0 += r[e]; s1 += r[e+1]; s2 += r[e+2]; s3 += r[e+3];
            }
            g_pooled1[(size_t)blk * P1_RPB + t] =
                ((s0 + s1) + (s2 + s3) + r[48]) * (1.0f / 49.0f);
        }
    }
}

// ---------------- fused head tile: smem-tiled GEMM + softmax-CE ------------
// (R4-proven: MB=16, 256 threads = 4 b-groups x 64 k-groups, 4b x TK tiles)
#define SMEM_BYTES (4*(MB*CC + CC*PITCH0 + MB*PITCH0))   // 46336

template<int C, int K, int KPAD, int TK, int PITCH, int AOFF>
__device__ __forceinline__ void head_tile(
    const float* __restrict__ pooled,
    const float* __restrict__ W, const float* __restrict__ bias,
    const int* __restrict__ lut, const float* __restrict__ cw,
    const int* __restrict__ target, int m0, char* sraw)
{
    float (*sp)[CC]     = reinterpret_cast<float(*)[CC]>(sraw);
    float (*swt)[PITCH] = reinterpret_cast<float(*)[PITCH]>(sraw + sizeof(float)*MB*CC);
    float (*slg)[PITCH] = reinterpret_cast<float(*)[PITCH]>(sraw + sizeof(float)*(MB*CC + CC*PITCH));

    const int tid = threadIdx.x;
    const int ktg = tid & 63;
    const int bt  = tid >> 6;

    float acc[4][TK];
    #pragma unroll
    for (int j = 0; j < 4; j++)
        #pragma unroll
        for (int t = 0; t < TK; t++) acc[j][t] = 0.0f;

    for (int c0 = 0; c0 < C; c0 += CC) {
        {
            const int row = tid >> 4;
            const int c4  = tid & 15;
            float4 v = *reinterpret_cast<const float4*>(
                pooled + (size_t)(m0 + row) * C + c0 + c4 * 4);
            *reinterpret_cast<float4*>(&sp[row][c4 * 4]) = v;
        }
        #pragma unroll
        for (int idx = tid; idx < KPAD * CC; idx += 256) {
            const int c = idx & (CC - 1);
            const int k = idx >> 6;
            swt[c][k] = (k < K) ? W[(size_t)k * C + c0 + c] : 0.0f;
        }
        __syncthreads();

        #pragma unroll 4
        for (int c4 = 0; c4 < CC / 4; c4++) {
            float pv[4][4];
            #pragma unroll
            for (int j = 0; j < 4; j++) {
                float4 v = *reinterpret_cast<const float4*>(&sp[bt * 4 + j][c4 * 4]);
                pv[j][0] = v.x; pv[j][1] = v.y; pv[j][2] = v.z; pv[j][3] = v.w;
            }
            #pragma unroll
            for (int cc = 0; cc < 4; cc++) {
                const int c = c4 * 4 + cc;
                if (TK == 2) {
                    float2 wv = *reinterpret_cast<const float2*>(&swt[c][ktg * 2]);
                    #pragma unroll
                    for (int j = 0; j < 4; j++) {
                        acc[j][0] = fmaf(pv[j][cc], wv.x, acc[j][0]);
                        acc[j][1] = fmaf(pv[j][cc], wv.y, acc[j][1]);
                    }
                } else {
                    float wv = swt[c][ktg];
                    #pragma unroll
                    for (int j = 0; j < 4; j++)
                        acc[j][0] = fmaf(pv[j][cc], wv, acc[j][0]);
                }
            }
        }
        __syncthreads();
    }

    #pragma unroll
    for (int t = 0; t < TK; t++) {
        const int k = ktg * TK + t;
        const float bv = (k < K) ? bias[k] : 0.0f;
        #pragma unroll
        for (int j = 0; j < 4; j++)
            slg[bt * 4 + j][k] = acc[j][t] + bv;
    }
    __syncthreads();

    const int w = tid >> 5, lane = tid & 31;
    #pragma unroll
    for (int r = w; r < MB; r += 8) {
        float m = -3.4e38f;
        for (int k = lane; k < K; k += 32) m = fmaxf(m, slg[r][k]);
        #pragma unroll
        for (int o = 16; o; o >>= 1) m = fmaxf(m, __shfl_xor_sync(0xffffffffu, m, o));
        float s = 0.0f;
        for (int k = lane; k < K; k += 32) s += __expf(slg[r][k] - m);
        #pragma unroll
        for (int o = 16; o; o >>= 1) s += __shfl_xor_sync(0xffffffffu, s, o);
        if (lane == 0) {
            const int b = m0 + r;
            const int t = lut[target[b]];
            const float nll = m + __logf(s) - slg[r][t];
            const float wt  = cw[t];
            atomicAdd(&g_accum[AOFF],     wt * nll);
            atomicAdd(&g_accum[AOFF + 1], wt);
        }
    }
}

// heads + in-kernel finalize: last block computes out[0] and resets state.
__global__ void __launch_bounds__(256)
heads_kernel(const float* __restrict__ W0, const float* __restrict__ b0v,
             const int* __restrict__ lut0, const float* __restrict__ cw0,
             const float* __restrict__ W1, const float* __restrict__ b1v,
             const int* __restrict__ lut1, const float* __restrict__ cw1,
             const int* __restrict__ target, float* __restrict__ out)
{
    __shared__ __align__(16) char sraw[SMEM_BYTES];
    const unsigned nblocks = 2u * (BATCH / MB);
    if (blockIdx.x < BATCH / MB)
        head_tile<C0_, K0_, KP0, 2, PITCH0, 0>(
            g_pooled0, W0, b0v, lut0, cw0, target, blockIdx.x * MB, sraw);
    else
        head_tile<C1_, K1_, KP1, 1, PITCH1, 2>(
            g_pooled1, W1, b1v, lut1, cw1, target,
            (blockIdx.x - BATCH / MB) * MB, sraw);

    __syncthreads();
    if (threadIdx.x == 0) {
        __threadfence();
        const unsigned arrived = atomicAdd(&g_done, 1u);
        if (arrived == nblocks - 1u) {
            const float n0 = atomicAdd(&g_accum[0], 0.0f);
            const float d0 = atomicAdd(&g_accum[1], 0.0f);
            const float n1 = atomicAdd(&g_accum[2], 0.0f);
            const float d1 = atomicAdd(&g_accum[3], 0.0f);
            out[0] = n0 / d0 + n1 / d1;
            atomicExch(&g_accum[0], 0.0f);
            atomicExch(&g_accum[1], 0.0f);
            atomicExch(&g_accum[2], 0.0f);
            atomicExch(&g_accum[3], 0.0f);
            __threadfence();
            atomicExch(&g_done, 0u);
        }
    }
}

// ---------------- launch ----------------
extern "C" void kernel_launch(void* const* d_in, const int* in_sizes, int n_in,
                              void* d_out, int out_size) {
    (void)in_sizes; (void)n_in; (void)out_size;
    const float* feat0  = (const float*)d_in[0];
    const float* feat1  = (const float*)d_in[1];
    const float* W0     = (const float*)d_in[2];
    const float* b0v    = (const float*)d_in[3];
    const float* W1     = (const float*)d_in[4];
    const float* b1v    = (const float*)d_in[5];
    const int*   lut0   = (const int*)d_in[6];
    const int*   lut1   = (const int*)d_in[7];
    const float* cw0    = (const float*)d_in[8];
    const float* cw1    = (const float*)d_in[9];
    const int*   target = (const int*)d_in[10];
    float* out = (float*)d_out;

    pool_kernel<<<NB0 + NB1, 256>>>(feat0, feat1);
    heads_kernel<<<2 * (BATCH / MB), 256>>>(W0, b0v, lut0, cw0,
                                            W1, b1v, lut1, cw1, target, out);
}